// round 2
// baseline (speedup 1.0000x reference)
#include <cuda_runtime.h>
#include <cuda_bf16.h>
#include <math.h>

#define N_NODES 50000
#define N_EDGES 800000
#define D 128
#define D4 (D / 4)
#define LN_EPS 1e-12f
#define TILE_N 64

// ---------------- scratch (no allocation allowed) ----------------
__device__ __align__(16) float g_h0[N_NODES * D];
__device__ __align__(16) float g_h1[N_NODES * D];
__device__ __align__(16) float g_agg[N_NODES * D];
__device__ __align__(16) float g_cnt[N_NODES];

// ---------------- kernels ----------------

__global__ void zero_kernel(float4* __restrict__ p, int n4) {
    int i = blockIdx.x * blockDim.x + threadIdx.x;
    int stride = gridDim.x * blockDim.x;
    float4 z = make_float4(0.f, 0.f, 0.f, 0.f);
    for (; i < n4; i += stride) p[i] = z;
}

// Sum of 4 embedding lookups + LayerNorm. One block (128 threads) per node.
__global__ void embed_ln_kernel(const int* __restrict__ x,
                                const float* __restrict__ syn,
                                const float* __restrict__ lem,
                                const float* __restrict__ pos,
                                const float* __restrict__ sen,
                                const float* __restrict__ g,
                                const float* __restrict__ b,
                                float* __restrict__ out) {
    int node = blockIdx.x;
    int t = threadIdx.x;
    int4 xi = ((const int4*)x)[node];  // cols 0..3
    // x[:,0]->syn, x[:,1]->pos, x[:,2]->sen, x[:,3]->lem
    float f = syn[(long)xi.x * D + t] + pos[(long)xi.y * D + t] +
              sen[(long)xi.z * D + t] + lem[(long)xi.w * D + t];

    __shared__ float red1[4];
    __shared__ float red2[4];
    int w = t >> 5, l = t & 31;

    float s = f;
    #pragma unroll
    for (int o = 16; o > 0; o >>= 1) s += __shfl_xor_sync(0xffffffffu, s, o);
    if (l == 0) red1[w] = s;
    __syncthreads();
    float mu = (red1[0] + red1[1] + red1[2] + red1[3]) * (1.0f / D);

    float d = f - mu;
    float v = d * d;
    #pragma unroll
    for (int o = 16; o > 0; o >>= 1) v += __shfl_xor_sync(0xffffffffu, v, o);
    if (l == 0) red2[w] = v;
    __syncthreads();
    float var = (red2[0] + red2[1] + red2[2] + red2[3]) * (1.0f / D);

    out[node * D + t] = d * rsqrtf(var + LN_EPS) * g[t] + b[t];
}

// In-degree count (float).
__global__ void count_kernel(const int* __restrict__ ei, float* __restrict__ cnt) {
    int e = blockIdx.x * blockDim.x + threadIdx.x;
    if (e < N_EDGES) atomicAdd(&cnt[ei[N_EDGES + e]], 1.0f);
}

// Scatter-add h[src] into agg[dst]. One warp per edge; each lane handles one
// float4 chunk. Vector L2 reduction (red.global.add.v4.f32, sm_90+).
__global__ void scatter_kernel(const float* __restrict__ h,
                               const int* __restrict__ ei,
                               float* __restrict__ agg) {
    int gtid = blockIdx.x * blockDim.x + threadIdx.x;
    int e = gtid >> 5;
    int lane = gtid & 31;
    if (e >= N_EDGES) return;
    int src = ei[e];             // uniform within warp -> broadcast load
    int dst = ei[N_EDGES + e];   // uniform within warp -> broadcast load
    float4 v = ((const float4*)h)[src * D4 + lane];
    float4* p = ((float4*)agg) + dst * D4 + lane;
    asm volatile("red.global.add.v4.f32 [%0], {%1, %2, %3, %4};"
                 :: "l"(p), "f"(v.x), "f"(v.y), "f"(v.z), "f"(v.w)
                 : "memory");
}

// out[n][c] = act( (agg[n]/max(cnt,1)) . Wl[c] + bl[c] + h[n] . Wr[c] )
// Block: 64 nodes x 128 cols, 256 threads, thread tile 8 nodes x 4 cols.
__global__ __launch_bounds__(256)
void combine_kernel(const float* __restrict__ agg,
                    const float* __restrict__ cnt,
                    const float* __restrict__ h,
                    const float* __restrict__ Wl,
                    const float* __restrict__ bl,
                    const float* __restrict__ Wr,
                    float* __restrict__ out,
                    int relu) {
    extern __shared__ float smem[];
    float* sa = smem;               // [TILE_N][D]
    float* sh = smem + TILE_N * D;  // [TILE_N][D]

    int n0 = blockIdx.x * TILE_N;
    int t = threadIdx.x;

    // stage tiles (agg pre-scaled by 1/deg)
    for (int i = t; i < TILE_N * D4; i += 256) {
        int r = i / D4;
        int c4 = i % D4;
        int node = n0 + r;
        float4 av = make_float4(0.f, 0.f, 0.f, 0.f);
        float4 hv = av;
        if (node < N_NODES) {
            float inv = 1.0f / fmaxf(cnt[node], 1.0f);
            av = ((const float4*)agg)[node * D4 + c4];
            av.x *= inv; av.y *= inv; av.z *= inv; av.w *= inv;
            hv = ((const float4*)h)[node * D4 + c4];
        }
        ((float4*)&sa[r * D])[c4] = av;
        ((float4*)&sh[r * D])[c4] = hv;
    }
    __syncthreads();

    int cx = (t & 31) * 4;   // column base (0..124)
    int ny = (t >> 5) * 8;   // node base within tile (0..56)

    float acc[8][4];
    #pragma unroll
    for (int n = 0; n < 8; n++)
        #pragma unroll
        for (int j = 0; j < 4; j++) acc[n][j] = 0.f;

    for (int k = 0; k < D; k += 4) {
        float4 wl[4], wr[4];
        #pragma unroll
        for (int j = 0; j < 4; j++) {
            wl[j] = __ldg((const float4*)&Wl[(cx + j) * D + k]);
            wr[j] = __ldg((const float4*)&Wr[(cx + j) * D + k]);
        }
        #pragma unroll
        for (int n = 0; n < 8; n++) {
            float4 a4 = *(const float4*)&sa[(ny + n) * D + k];
            float4 h4 = *(const float4*)&sh[(ny + n) * D + k];
            #pragma unroll
            for (int j = 0; j < 4; j++) {
                float r = acc[n][j];
                r = fmaf(a4.x, wl[j].x, r);
                r = fmaf(a4.y, wl[j].y, r);
                r = fmaf(a4.z, wl[j].z, r);
                r = fmaf(a4.w, wl[j].w, r);
                r = fmaf(h4.x, wr[j].x, r);
                r = fmaf(h4.y, wr[j].y, r);
                r = fmaf(h4.z, wr[j].z, r);
                r = fmaf(h4.w, wr[j].w, r);
                acc[n][j] = r;
            }
        }
    }

    float4 bias = __ldg((const float4*)&bl[cx]);
    #pragma unroll
    for (int n = 0; n < 8; n++) {
        int node = n0 + ny + n;
        if (node < N_NODES) {
            float4 o;
            o.x = acc[n][0] + bias.x;
            o.y = acc[n][1] + bias.y;
            o.z = acc[n][2] + bias.z;
            o.w = acc[n][3] + bias.w;
            if (relu) {
                o.x = fmaxf(o.x, 0.f);
                o.y = fmaxf(o.y, 0.f);
                o.z = fmaxf(o.z, 0.f);
                o.w = fmaxf(o.w, 0.f);
            }
            ((float4*)out)[node * D4 + (cx >> 2)] = o;
        }
    }
}

// ---------------- launch ----------------

extern "C" void kernel_launch(void* const* d_in, const int* in_sizes, int n_in,
                              void* d_out, int out_size) {
    const int*   x    = (const int*)d_in[0];
    const int*   ei   = (const int*)d_in[1];
    const float* syn  = (const float*)d_in[2];
    const float* lem  = (const float*)d_in[3];
    const float* pos  = (const float*)d_in[4];
    const float* sen  = (const float*)d_in[5];
    const float* ln_g = (const float*)d_in[6];
    const float* ln_b = (const float*)d_in[7];
    const float* Wl0  = (const float*)d_in[8];
    const float* bl0  = (const float*)d_in[9];
    const float* Wr0  = (const float*)d_in[10];
    const float* Wl1  = (const float*)d_in[11];
    const float* bl1  = (const float*)d_in[12];
    const float* Wr1  = (const float*)d_in[13];
    float* out = (float*)d_out;

    float *h0, *h1, *agg, *cnt;
    cudaGetSymbolAddress((void**)&h0,  g_h0);
    cudaGetSymbolAddress((void**)&h1,  g_h1);
    cudaGetSymbolAddress((void**)&agg, g_agg);
    cudaGetSymbolAddress((void**)&cnt, g_cnt);

    static const int smem_bytes = TILE_N * D * 4 * 2;  // 64 KB
    cudaFuncSetAttribute(combine_kernel,
                         cudaFuncAttributeMaxDynamicSharedMemorySize, smem_bytes);

    const int agg4 = N_NODES * D4;          // float4 count of agg
    const int cnt4 = (N_NODES + 3) / 4;     // float4 count of cnt (padded array is larger anyway? no)
    const int scatter_blocks = (N_EDGES * 32 + 255) / 256;
    const int combine_blocks = (N_NODES + TILE_N - 1) / TILE_N;

    // 1. embeddings + LayerNorm -> h0
    embed_ln_kernel<<<N_NODES, 128>>>(x, syn, lem, pos, sen, ln_g, ln_b, h0);

    // 2. zero agg + cnt, count degrees
    zero_kernel<<<4096, 256>>>((float4*)agg, agg4);
    zero_kernel<<<64, 256>>>((float4*)cnt, N_NODES / 4);       // 50000 % 4 == 0
    count_kernel<<<(N_EDGES + 255) / 256, 256>>>(ei, cnt);

    // 3. layer 0
    scatter_kernel<<<scatter_blocks, 256>>>(h0, ei, agg);
    combine_kernel<<<combine_blocks, 256, smem_bytes>>>(agg, cnt, h0,
                                                        Wl0, bl0, Wr0, h1, 1);

    // 4. layer 1
    zero_kernel<<<4096, 256>>>((float4*)agg, agg4);
    scatter_kernel<<<scatter_blocks, 256>>>(h1, ei, agg);
    combine_kernel<<<combine_blocks, 256, smem_bytes>>>(agg, cnt, h1,
                                                        Wl1, bl1, Wr1, out, 0);
}

// round 3
// speedup vs baseline: 1.0264x; 1.0264x over previous
#include <cuda_runtime.h>
#include <cuda_bf16.h>
#include <math.h>

#define N_NODES 50000
#define N_EDGES 800000
#define D 128
#define D4 (D / 4)
#define LN_EPS 1e-12f
#define TILE_N 64
#define SCAN_T 1024

// ---------------- scratch (no allocation allowed) ----------------
__device__ __align__(16) float g_h0[N_NODES * D];
__device__ __align__(16) float g_h1[N_NODES * D];
__device__ __align__(16) float g_agg[N_NODES * D];
__device__ int   g_deg[N_NODES];
__device__ int   g_row[N_NODES + 1];
__device__ int   g_cursor[N_NODES];
__device__ float g_invd[N_NODES];
__device__ int   g_perm[N_EDGES];

// ---------------- kernels ----------------

__global__ void zero_int_kernel(int* __restrict__ p, int n) {
    int i = blockIdx.x * blockDim.x + threadIdx.x;
    if (i < n) p[i] = 0;
}

// Sum of 4 embedding lookups + LayerNorm. One block (128 threads) per node.
__global__ void embed_ln_kernel(const int* __restrict__ x,
                                const float* __restrict__ syn,
                                const float* __restrict__ lem,
                                const float* __restrict__ pos,
                                const float* __restrict__ sen,
                                const float* __restrict__ g,
                                const float* __restrict__ b,
                                float* __restrict__ out) {
    int node = blockIdx.x;
    int t = threadIdx.x;
    int4 xi = ((const int4*)x)[node];  // cols 0..3
    // x[:,0]->syn, x[:,1]->pos, x[:,2]->sen, x[:,3]->lem
    float f = syn[(long)xi.x * D + t] + pos[(long)xi.y * D + t] +
              sen[(long)xi.z * D + t] + lem[(long)xi.w * D + t];

    __shared__ float red1[4];
    __shared__ float red2[4];
    int w = t >> 5, l = t & 31;

    float s = f;
    #pragma unroll
    for (int o = 16; o > 0; o >>= 1) s += __shfl_xor_sync(0xffffffffu, s, o);
    if (l == 0) red1[w] = s;
    __syncthreads();
    float mu = (red1[0] + red1[1] + red1[2] + red1[3]) * (1.0f / D);

    float d = f - mu;
    float v = d * d;
    #pragma unroll
    for (int o = 16; o > 0; o >>= 1) v += __shfl_xor_sync(0xffffffffu, v, o);
    if (l == 0) red2[w] = v;
    __syncthreads();
    float var = (red2[0] + red2[1] + red2[2] + red2[3]) * (1.0f / D);

    out[node * D + t] = d * rsqrtf(var + LN_EPS) * g[t] + b[t];
}

// In-degree count (int).
__global__ void count_kernel(const int* __restrict__ ei, int* __restrict__ deg) {
    int e = blockIdx.x * blockDim.x + threadIdx.x;
    if (e < N_EDGES) atomicAdd(&deg[ei[N_EDGES + e]], 1);
}

// Single-block exclusive scan over degrees -> row_ptr, cursor, inv_deg.
__global__ __launch_bounds__(SCAN_T)
void scan_kernel(const int* __restrict__ deg,
                 int* __restrict__ row,
                 int* __restrict__ cursor,
                 float* __restrict__ invd) {
    __shared__ int ssum[SCAN_T];
    int t = threadIdx.x;
    const int CH = (N_NODES + SCAN_T - 1) / SCAN_T;  // 49
    int beg = t * CH;
    int end = min(beg + CH, N_NODES);

    int s = 0;
    for (int i = beg; i < end; i++) s += deg[i];
    ssum[t] = s;
    __syncthreads();

    // Hillis-Steele inclusive scan
    for (int o = 1; o < SCAN_T; o <<= 1) {
        int v = (t >= o) ? ssum[t - o] : 0;
        __syncthreads();
        ssum[t] += v;
        __syncthreads();
    }

    int running = ssum[t] - s;  // exclusive offset for this chunk
    for (int i = beg; i < end; i++) {
        int d = deg[i];
        row[i] = running;
        cursor[i] = running;
        invd[i] = 1.0f / fmaxf((float)d, 1.0f);
        running += d;
    }
    if (t == SCAN_T - 1) row[N_NODES] = ssum[SCAN_T - 1];
}

// Fill permutation: for each edge, place src into dst's CSR segment.
__global__ void build_perm_kernel(const int* __restrict__ ei,
                                  int* __restrict__ cursor,
                                  int* __restrict__ perm) {
    int e = blockIdx.x * blockDim.x + threadIdx.x;
    if (e >= N_EDGES) return;
    int dst = ei[N_EDGES + e];
    int pos = atomicAdd(&cursor[dst], 1);
    perm[pos] = ei[e];
}

// Mean-aggregate via CSR gather. One warp per node; lane = float4 chunk.
__global__ __launch_bounds__(128)
void gather_agg_kernel(const float* __restrict__ h,
                       const int* __restrict__ row,
                       const int* __restrict__ perm,
                       const float* __restrict__ invd,
                       float* __restrict__ agg) {
    int node = blockIdx.x * 4 + (threadIdx.x >> 5);
    int lane = threadIdx.x & 31;
    if (node >= N_NODES) return;
    int beg = row[node];
    int end = row[node + 1];

    float4 acc = make_float4(0.f, 0.f, 0.f, 0.f);
    for (int j = beg; j < end; j += 32) {
        int nj = min(32, end - j);
        int s = (j + lane < end) ? perm[j + lane] : 0;
        int k = 0;
        // process 4 neighbors at a time for MLP
        for (; k + 4 <= nj; k += 4) {
            int s0 = __shfl_sync(0xffffffffu, s, k);
            int s1 = __shfl_sync(0xffffffffu, s, k + 1);
            int s2 = __shfl_sync(0xffffffffu, s, k + 2);
            int s3 = __shfl_sync(0xffffffffu, s, k + 3);
            float4 v0 = ((const float4*)h)[s0 * D4 + lane];
            float4 v1 = ((const float4*)h)[s1 * D4 + lane];
            float4 v2 = ((const float4*)h)[s2 * D4 + lane];
            float4 v3 = ((const float4*)h)[s3 * D4 + lane];
            acc.x += v0.x + v1.x + v2.x + v3.x;
            acc.y += v0.y + v1.y + v2.y + v3.y;
            acc.z += v0.z + v1.z + v2.z + v3.z;
            acc.w += v0.w + v1.w + v2.w + v3.w;
        }
        for (; k < nj; k++) {
            int sk = __shfl_sync(0xffffffffu, s, k);
            float4 v = ((const float4*)h)[sk * D4 + lane];
            acc.x += v.x; acc.y += v.y; acc.z += v.z; acc.w += v.w;
        }
    }
    float iv = invd[node];
    acc.x *= iv; acc.y *= iv; acc.z *= iv; acc.w *= iv;
    ((float4*)agg)[node * D4 + lane] = acc;
}

// out[n][c] = act( agg[n] . Wl[c] + bl[c] + h[n] . Wr[c] )   (agg pre-scaled)
// Block: 64 nodes x 128 cols, 256 threads, thread tile 8 nodes x 4 cols.
__global__ __launch_bounds__(256)
void combine_kernel(const float* __restrict__ agg,
                    const float* __restrict__ h,
                    const float* __restrict__ Wl,
                    const float* __restrict__ bl,
                    const float* __restrict__ Wr,
                    float* __restrict__ out,
                    int relu) {
    extern __shared__ float smem[];
    float* sa = smem;               // [TILE_N][D]
    float* sh = smem + TILE_N * D;  // [TILE_N][D]

    int n0 = blockIdx.x * TILE_N;
    int t = threadIdx.x;

    for (int i = t; i < TILE_N * D4; i += 256) {
        int r = i / D4;
        int c4 = i % D4;
        int node = n0 + r;
        float4 av = make_float4(0.f, 0.f, 0.f, 0.f);
        float4 hv = av;
        if (node < N_NODES) {
            av = ((const float4*)agg)[node * D4 + c4];
            hv = ((const float4*)h)[node * D4 + c4];
        }
        ((float4*)&sa[r * D])[c4] = av;
        ((float4*)&sh[r * D])[c4] = hv;
    }
    __syncthreads();

    int cx = (t & 31) * 4;   // column base (0..124)
    int ny = (t >> 5) * 8;   // node base within tile (0..56)

    float acc[8][4];
    #pragma unroll
    for (int n = 0; n < 8; n++)
        #pragma unroll
        for (int j = 0; j < 4; j++) acc[n][j] = 0.f;

    for (int k = 0; k < D; k += 4) {
        float4 wl[4], wr[4];
        #pragma unroll
        for (int j = 0; j < 4; j++) {
            wl[j] = __ldg((const float4*)&Wl[(cx + j) * D + k]);
            wr[j] = __ldg((const float4*)&Wr[(cx + j) * D + k]);
        }
        #pragma unroll
        for (int n = 0; n < 8; n++) {
            float4 a4 = *(const float4*)&sa[(ny + n) * D + k];
            float4 h4 = *(const float4*)&sh[(ny + n) * D + k];
            #pragma unroll
            for (int j = 0; j < 4; j++) {
                float r = acc[n][j];
                r = fmaf(a4.x, wl[j].x, r);
                r = fmaf(a4.y, wl[j].y, r);
                r = fmaf(a4.z, wl[j].z, r);
                r = fmaf(a4.w, wl[j].w, r);
                r = fmaf(h4.x, wr[j].x, r);
                r = fmaf(h4.y, wr[j].y, r);
                r = fmaf(h4.z, wr[j].z, r);
                r = fmaf(h4.w, wr[j].w, r);
                acc[n][j] = r;
            }
        }
    }

    float4 bias = __ldg((const float4*)&bl[cx]);
    #pragma unroll
    for (int n = 0; n < 8; n++) {
        int node = n0 + ny + n;
        if (node < N_NODES) {
            float4 o;
            o.x = acc[n][0] + bias.x;
            o.y = acc[n][1] + bias.y;
            o.z = acc[n][2] + bias.z;
            o.w = acc[n][3] + bias.w;
            if (relu) {
                o.x = fmaxf(o.x, 0.f);
                o.y = fmaxf(o.y, 0.f);
                o.z = fmaxf(o.z, 0.f);
                o.w = fmaxf(o.w, 0.f);
            }
            ((float4*)out)[node * D4 + (cx >> 2)] = o;
        }
    }
}

// ---------------- launch ----------------

extern "C" void kernel_launch(void* const* d_in, const int* in_sizes, int n_in,
                              void* d_out, int out_size) {
    const int*   x    = (const int*)d_in[0];
    const int*   ei   = (const int*)d_in[1];
    const float* syn  = (const float*)d_in[2];
    const float* lem  = (const float*)d_in[3];
    const float* pos  = (const float*)d_in[4];
    const float* sen  = (const float*)d_in[5];
    const float* ln_g = (const float*)d_in[6];
    const float* ln_b = (const float*)d_in[7];
    const float* Wl0  = (const float*)d_in[8];
    const float* bl0  = (const float*)d_in[9];
    const float* Wr0  = (const float*)d_in[10];
    const float* Wl1  = (const float*)d_in[11];
    const float* bl1  = (const float*)d_in[12];
    const float* Wr1  = (const float*)d_in[13];
    float* out = (float*)d_out;

    float *h0, *h1, *agg, *invd;
    int *deg, *row, *cursor, *perm;
    cudaGetSymbolAddress((void**)&h0,     g_h0);
    cudaGetSymbolAddress((void**)&h1,     g_h1);
    cudaGetSymbolAddress((void**)&agg,    g_agg);
    cudaGetSymbolAddress((void**)&deg,    g_deg);
    cudaGetSymbolAddress((void**)&row,    g_row);
    cudaGetSymbolAddress((void**)&cursor, g_cursor);
    cudaGetSymbolAddress((void**)&invd,   g_invd);
    cudaGetSymbolAddress((void**)&perm,   g_perm);

    static const int smem_bytes = TILE_N * D * 4 * 2;  // 64 KB
    cudaFuncSetAttribute(combine_kernel,
                         cudaFuncAttributeMaxDynamicSharedMemorySize, smem_bytes);

    const int eblocks = (N_EDGES + 255) / 256;
    const int gather_blocks = (N_NODES + 3) / 4;
    const int combine_blocks = (N_NODES + TILE_N - 1) / TILE_N;

    // 1. embeddings + LayerNorm -> h0
    embed_ln_kernel<<<N_NODES, 128>>>(x, syn, lem, pos, sen, ln_g, ln_b, h0);

    // 2. CSR build
    zero_int_kernel<<<(N_NODES + 255) / 256, 256>>>(deg, N_NODES);
    count_kernel<<<eblocks, 256>>>(ei, deg);
    scan_kernel<<<1, SCAN_T>>>(deg, row, cursor, invd);
    build_perm_kernel<<<eblocks, 256>>>(ei, cursor, perm);

    // 3. layer 0
    gather_agg_kernel<<<gather_blocks, 128>>>(h0, row, perm, invd, agg);
    combine_kernel<<<combine_blocks, 256, smem_bytes>>>(agg, h0, Wl0, bl0, Wr0, h1, 1);

    // 4. layer 1
    gather_agg_kernel<<<gather_blocks, 128>>>(h1, row, perm, invd, agg);
    combine_kernel<<<combine_blocks, 256, smem_bytes>>>(agg, h1, Wl1, bl1, Wr1, out, 0);
}

// round 4
// speedup vs baseline: 1.1915x; 1.1608x over previous
#include <cuda_runtime.h>
#include <cuda_bf16.h>
#include <math.h>

#define N_NODES 50000
#define N_EDGES 800000
#define D 128
#define D4 (D / 4)
#define LN_EPS 1e-12f
#define TILE_N 64
#define SCAN_B 256
#define N_SB ((N_NODES + SCAN_B - 1) / SCAN_B)   // 196

// ---------------- scratch (no allocation allowed) ----------------
__device__ __align__(16) float g_h0[N_NODES * D];
__device__ __align__(16) float g_h1[N_NODES * D];
__device__ __align__(16) float g_agg[N_NODES * D];
__device__ int   g_deg[N_NODES];
__device__ int   g_row[N_NODES + 1];
__device__ int   g_cursor[N_NODES];
__device__ float g_invd[N_NODES];
__device__ int   g_perm[N_EDGES];
__device__ int   g_bsum[N_SB];
__device__ int   g_boff[N_SB];

// ---------------- kernels ----------------

__global__ void zero_int_kernel(int* __restrict__ p, int n) {
    int i = blockIdx.x * blockDim.x + threadIdx.x;
    if (i < n) p[i] = 0;
}

// Sum of 4 embedding lookups + LayerNorm. One block (128 threads) per node.
__global__ void embed_ln_kernel(const int* __restrict__ x,
                                const float* __restrict__ syn,
                                const float* __restrict__ lem,
                                const float* __restrict__ pos,
                                const float* __restrict__ sen,
                                const float* __restrict__ g,
                                const float* __restrict__ b,
                                float* __restrict__ out) {
    int node = blockIdx.x;
    int t = threadIdx.x;
    int4 xi = ((const int4*)x)[node];  // cols 0..3
    // x[:,0]->syn, x[:,1]->pos, x[:,2]->sen, x[:,3]->lem
    float f = syn[(long)xi.x * D + t] + pos[(long)xi.y * D + t] +
              sen[(long)xi.z * D + t] + lem[(long)xi.w * D + t];

    __shared__ float red1[4];
    __shared__ float red2[4];
    int w = t >> 5, l = t & 31;

    float s = f;
    #pragma unroll
    for (int o = 16; o > 0; o >>= 1) s += __shfl_xor_sync(0xffffffffu, s, o);
    if (l == 0) red1[w] = s;
    __syncthreads();
    float mu = (red1[0] + red1[1] + red1[2] + red1[3]) * (1.0f / D);

    float d = f - mu;
    float v = d * d;
    #pragma unroll
    for (int o = 16; o > 0; o >>= 1) v += __shfl_xor_sync(0xffffffffu, v, o);
    if (l == 0) red2[w] = v;
    __syncthreads();
    float var = (red2[0] + red2[1] + red2[2] + red2[3]) * (1.0f / D);

    out[node * D + t] = d * rsqrtf(var + LN_EPS) * g[t] + b[t];
}

// In-degree count (int).
__global__ void count_kernel(const int* __restrict__ ei, int* __restrict__ deg) {
    int e = blockIdx.x * blockDim.x + threadIdx.x;
    if (e < N_EDGES) atomicAdd(&deg[ei[N_EDGES + e]], 1);
}

// Phase 1: per-block sum of 256 degrees.
__global__ __launch_bounds__(SCAN_B)
void block_sum_kernel(const int* __restrict__ deg, int* __restrict__ bsum) {
    __shared__ int ws[8];
    int node = blockIdx.x * SCAN_B + threadIdx.x;
    int d = (node < N_NODES) ? deg[node] : 0;
    int s = d;
    #pragma unroll
    for (int o = 16; o > 0; o >>= 1) s += __shfl_xor_sync(0xffffffffu, s, o);
    int w = threadIdx.x >> 5, l = threadIdx.x & 31;
    if (l == 0) ws[w] = s;
    __syncthreads();
    if (threadIdx.x == 0) {
        int tot = 0;
        #pragma unroll
        for (int i = 0; i < 8; i++) tot += ws[i];
        bsum[blockIdx.x] = tot;
    }
}

// Phase 2: exclusive scan of N_SB block sums. One block of 256 threads.
__global__ __launch_bounds__(256)
void scan_bsums_kernel(const int* __restrict__ bsum, int* __restrict__ boff) {
    __shared__ int sm[256];
    int t = threadIdx.x;
    int v = (t < N_SB) ? bsum[t] : 0;
    sm[t] = v;
    __syncthreads();
    for (int o = 1; o < 256; o <<= 1) {
        int u = (t >= o) ? sm[t - o] : 0;
        __syncthreads();
        sm[t] += u;
        __syncthreads();
    }
    if (t < N_SB) boff[t] = sm[t] - v;  // exclusive
}

// Phase 3: per-block exclusive scan + base offset -> row, cursor, invd.
__global__ __launch_bounds__(SCAN_B)
void expand_kernel(const int* __restrict__ deg,
                   const int* __restrict__ boff,
                   int* __restrict__ row,
                   int* __restrict__ cursor,
                   float* __restrict__ invd) {
    __shared__ int ws[8];
    __shared__ int wo[8];
    int t = threadIdx.x;
    int node = blockIdx.x * SCAN_B + t;
    int d = (node < N_NODES) ? deg[node] : 0;

    int incl = d;
    int l = t & 31, w = t >> 5;
    #pragma unroll
    for (int o = 1; o < 32; o <<= 1) {
        int u = __shfl_up_sync(0xffffffffu, incl, o);
        if (l >= o) incl += u;
    }
    if (l == 31) ws[w] = incl;
    __syncthreads();
    if (t == 0) {
        int run = 0;
        #pragma unroll
        for (int i = 0; i < 8; i++) { wo[i] = run; run += ws[i]; }
    }
    __syncthreads();

    if (node < N_NODES) {
        int excl = boff[blockIdx.x] + wo[w] + incl - d;
        row[node] = excl;
        cursor[node] = excl;
        invd[node] = 1.0f / fmaxf((float)d, 1.0f);
    }
    if (node == 0) row[N_NODES] = N_EDGES;
}

// Fill permutation: for each edge, place src into dst's CSR segment.
__global__ void build_perm_kernel(const int* __restrict__ ei,
                                  int* __restrict__ cursor,
                                  int* __restrict__ perm) {
    int e = blockIdx.x * blockDim.x + threadIdx.x;
    if (e >= N_EDGES) return;
    int dst = ei[N_EDGES + e];
    int pos = atomicAdd(&cursor[dst], 1);
    perm[pos] = ei[e];
}

// Mean-aggregate via CSR gather. One warp per node; lane = float4 chunk.
__global__ __launch_bounds__(128)
void gather_agg_kernel(const float* __restrict__ h,
                       const int* __restrict__ row,
                       const int* __restrict__ perm,
                       const float* __restrict__ invd,
                       float* __restrict__ agg) {
    int node = blockIdx.x * 4 + (threadIdx.x >> 5);
    int lane = threadIdx.x & 31;
    if (node >= N_NODES) return;
    int beg = row[node];
    int end = row[node + 1];

    float4 acc = make_float4(0.f, 0.f, 0.f, 0.f);
    for (int j = beg; j < end; j += 32) {
        int nj = min(32, end - j);
        int s = (j + lane < end) ? perm[j + lane] : 0;
        int k = 0;
        for (; k + 4 <= nj; k += 4) {
            int s0 = __shfl_sync(0xffffffffu, s, k);
            int s1 = __shfl_sync(0xffffffffu, s, k + 1);
            int s2 = __shfl_sync(0xffffffffu, s, k + 2);
            int s3 = __shfl_sync(0xffffffffu, s, k + 3);
            float4 v0 = ((const float4*)h)[s0 * D4 + lane];
            float4 v1 = ((const float4*)h)[s1 * D4 + lane];
            float4 v2 = ((const float4*)h)[s2 * D4 + lane];
            float4 v3 = ((const float4*)h)[s3 * D4 + lane];
            acc.x += v0.x + v1.x + v2.x + v3.x;
            acc.y += v0.y + v1.y + v2.y + v3.y;
            acc.z += v0.z + v1.z + v2.z + v3.z;
            acc.w += v0.w + v1.w + v2.w + v3.w;
        }
        for (; k < nj; k++) {
            int sk = __shfl_sync(0xffffffffu, s, k);
            float4 v = ((const float4*)h)[sk * D4 + lane];
            acc.x += v.x; acc.y += v.y; acc.z += v.z; acc.w += v.w;
        }
    }
    float iv = invd[node];
    acc.x *= iv; acc.y *= iv; acc.z *= iv; acc.w *= iv;
    ((float4*)agg)[node * D4 + lane] = acc;
}

// out[n][c] = act( agg[n] . Wl[c] + bl[c] + h[n] . Wr[c] )   (agg pre-scaled)
// Block: 64 nodes x 128 cols, 256 threads, thread tile 8 nodes x 4 cols.
__global__ __launch_bounds__(256)
void combine_kernel(const float* __restrict__ agg,
                    const float* __restrict__ h,
                    const float* __restrict__ Wl,
                    const float* __restrict__ bl,
                    const float* __restrict__ Wr,
                    float* __restrict__ out,
                    int relu) {
    extern __shared__ float smem[];
    float* sa = smem;               // [TILE_N][D]
    float* sh = smem + TILE_N * D;  // [TILE_N][D]

    int n0 = blockIdx.x * TILE_N;
    int t = threadIdx.x;

    for (int i = t; i < TILE_N * D4; i += 256) {
        int r = i / D4;
        int c4 = i % D4;
        int node = n0 + r;
        float4 av = make_float4(0.f, 0.f, 0.f, 0.f);
        float4 hv = av;
        if (node < N_NODES) {
            av = ((const float4*)agg)[node * D4 + c4];
            hv = ((const float4*)h)[node * D4 + c4];
        }
        ((float4*)&sa[r * D])[c4] = av;
        ((float4*)&sh[r * D])[c4] = hv;
    }
    __syncthreads();

    int cx = (t & 31) * 4;   // column base (0..124)
    int ny = (t >> 5) * 8;   // node base within tile (0..56)

    float acc[8][4];
    #pragma unroll
    for (int n = 0; n < 8; n++)
        #pragma unroll
        for (int j = 0; j < 4; j++) acc[n][j] = 0.f;

    for (int k = 0; k < D; k += 4) {
        float4 wl[4], wr[4];
        #pragma unroll
        for (int j = 0; j < 4; j++) {
            wl[j] = __ldg((const float4*)&Wl[(cx + j) * D + k]);
            wr[j] = __ldg((const float4*)&Wr[(cx + j) * D + k]);
        }
        #pragma unroll
        for (int n = 0; n < 8; n++) {
            float4 a4 = *(const float4*)&sa[(ny + n) * D + k];
            float4 h4 = *(const float4*)&sh[(ny + n) * D + k];
            #pragma unroll
            for (int j = 0; j < 4; j++) {
                float r = acc[n][j];
                r = fmaf(a4.x, wl[j].x, r);
                r = fmaf(a4.y, wl[j].y, r);
                r = fmaf(a4.z, wl[j].z, r);
                r = fmaf(a4.w, wl[j].w, r);
                r = fmaf(h4.x, wr[j].x, r);
                r = fmaf(h4.y, wr[j].y, r);
                r = fmaf(h4.z, wr[j].z, r);
                r = fmaf(h4.w, wr[j].w, r);
                acc[n][j] = r;
            }
        }
    }

    float4 bias = __ldg((const float4*)&bl[cx]);
    #pragma unroll
    for (int n = 0; n < 8; n++) {
        int node = n0 + ny + n;
        if (node < N_NODES) {
            float4 o;
            o.x = acc[n][0] + bias.x;
            o.y = acc[n][1] + bias.y;
            o.z = acc[n][2] + bias.z;
            o.w = acc[n][3] + bias.w;
            if (relu) {
                o.x = fmaxf(o.x, 0.f);
                o.y = fmaxf(o.y, 0.f);
                o.z = fmaxf(o.z, 0.f);
                o.w = fmaxf(o.w, 0.f);
            }
            ((float4*)out)[node * D4 + (cx >> 2)] = o;
        }
    }
}

// ---------------- launch ----------------

extern "C" void kernel_launch(void* const* d_in, const int* in_sizes, int n_in,
                              void* d_out, int out_size) {
    const int*   x    = (const int*)d_in[0];
    const int*   ei   = (const int*)d_in[1];
    const float* syn  = (const float*)d_in[2];
    const float* lem  = (const float*)d_in[3];
    const float* pos  = (const float*)d_in[4];
    const float* sen  = (const float*)d_in[5];
    const float* ln_g = (const float*)d_in[6];
    const float* ln_b = (const float*)d_in[7];
    const float* Wl0  = (const float*)d_in[8];
    const float* bl0  = (const float*)d_in[9];
    const float* Wr0  = (const float*)d_in[10];
    const float* Wl1  = (const float*)d_in[11];
    const float* bl1  = (const float*)d_in[12];
    const float* Wr1  = (const float*)d_in[13];
    float* out = (float*)d_out;

    float *h0, *h1, *agg, *invd;
    int *deg, *row, *cursor, *perm, *bsum, *boff;
    cudaGetSymbolAddress((void**)&h0,     g_h0);
    cudaGetSymbolAddress((void**)&h1,     g_h1);
    cudaGetSymbolAddress((void**)&agg,    g_agg);
    cudaGetSymbolAddress((void**)&deg,    g_deg);
    cudaGetSymbolAddress((void**)&row,    g_row);
    cudaGetSymbolAddress((void**)&cursor, g_cursor);
    cudaGetSymbolAddress((void**)&invd,   g_invd);
    cudaGetSymbolAddress((void**)&perm,   g_perm);
    cudaGetSymbolAddress((void**)&bsum,   g_bsum);
    cudaGetSymbolAddress((void**)&boff,   g_boff);

    static const int smem_bytes = TILE_N * D * 4 * 2;  // 64 KB
    cudaFuncSetAttribute(combine_kernel,
                         cudaFuncAttributeMaxDynamicSharedMemorySize, smem_bytes);

    const int eblocks = (N_EDGES + 255) / 256;
    const int gather_blocks = (N_NODES + 3) / 4;
    const int combine_blocks = (N_NODES + TILE_N - 1) / TILE_N;

    // 1. embeddings + LayerNorm -> h0
    embed_ln_kernel<<<N_NODES, 128>>>(x, syn, lem, pos, sen, ln_g, ln_b, h0);

    // 2. CSR build (parallel scan)
    zero_int_kernel<<<(N_NODES + 255) / 256, 256>>>(deg, N_NODES);
    count_kernel<<<eblocks, 256>>>(ei, deg);
    block_sum_kernel<<<N_SB, SCAN_B>>>(deg, bsum);
    scan_bsums_kernel<<<1, 256>>>(bsum, boff);
    expand_kernel<<<N_SB, SCAN_B>>>(deg, boff, row, cursor, invd);
    build_perm_kernel<<<eblocks, 256>>>(ei, cursor, perm);

    // 3. layer 0
    gather_agg_kernel<<<gather_blocks, 128>>>(h0, row, perm, invd, agg);
    combine_kernel<<<combine_blocks, 256, smem_bytes>>>(agg, h0, Wl0, bl0, Wr0, h1, 1);

    // 4. layer 1
    gather_agg_kernel<<<gather_blocks, 128>>>(h1, row, perm, invd, agg);
    combine_kernel<<<combine_blocks, 256, smem_bytes>>>(agg, h1, Wl1, bl1, Wr1, out, 0);
}

// round 5
// speedup vs baseline: 2.3931x; 2.0085x over previous
#include <cuda_runtime.h>
#include <cuda_bf16.h>
#include <math.h>

#define N_NODES 50000
#define N_EDGES 800000
#define D 128
#define D4 (D / 4)
#define LN_EPS 1e-12f
#define TILE_N 64
#define SCAN_B 256
#define N_SB ((N_NODES + SCAN_B - 1) / SCAN_B)   // 196

// ---------------- scratch (no allocation allowed) ----------------
__device__ __align__(16) float g_h0[N_NODES * D];
__device__ __align__(16) float g_h1[N_NODES * D];
__device__ __align__(16) float g_agg[N_NODES * D];
__device__ __align__(16) float g_WT[4][D * D];   // Wl0^T, Wr0^T, Wl1^T, Wr1^T (as WT[k][c])
__device__ int   g_deg[N_NODES];
__device__ int   g_row[N_NODES + 1];
__device__ int   g_cursor[N_NODES];
__device__ float g_invd[N_NODES];
__device__ int   g_perm[N_EDGES];
__device__ int   g_bsum[N_SB];
__device__ int   g_boff[N_SB];

// ---------------- kernels ----------------

__global__ void zero_int_kernel(int* __restrict__ p, int n) {
    int i = blockIdx.x * blockDim.x + threadIdx.x;
    if (i < n) p[i] = 0;
}

// Transpose a DxD matrix: wt[k*D + c] = w[c*D + k]. Grid-stride, 4 matrices.
__global__ void transpose_w_kernel(const float* __restrict__ w0,
                                   const float* __restrict__ w1,
                                   const float* __restrict__ w2,
                                   const float* __restrict__ w3,
                                   float* __restrict__ wt) {
    int i = blockIdx.x * blockDim.x + threadIdx.x;   // 0 .. 4*D*D-1
    if (i >= 4 * D * D) return;
    int m = i / (D * D);
    int r = (i % (D * D)) / D;   // source row c
    int k = i % D;               // source col k
    const float* w = (m == 0) ? w0 : (m == 1) ? w1 : (m == 2) ? w2 : w3;
    wt[m * D * D + k * D + r] = w[r * D + k];
}

// Sum of 4 embedding lookups + LayerNorm. One block (128 threads) per node.
__global__ void embed_ln_kernel(const int* __restrict__ x,
                                const float* __restrict__ syn,
                                const float* __restrict__ lem,
                                const float* __restrict__ pos,
                                const float* __restrict__ sen,
                                const float* __restrict__ g,
                                const float* __restrict__ b,
                                float* __restrict__ out) {
    int node = blockIdx.x;
    int t = threadIdx.x;
    int4 xi = ((const int4*)x)[node];  // cols 0..3
    float f = syn[(long)xi.x * D + t] + pos[(long)xi.y * D + t] +
              sen[(long)xi.z * D + t] + lem[(long)xi.w * D + t];

    __shared__ float red1[4];
    __shared__ float red2[4];
    int w = t >> 5, l = t & 31;

    float s = f;
    #pragma unroll
    for (int o = 16; o > 0; o >>= 1) s += __shfl_xor_sync(0xffffffffu, s, o);
    if (l == 0) red1[w] = s;
    __syncthreads();
    float mu = (red1[0] + red1[1] + red1[2] + red1[3]) * (1.0f / D);

    float d = f - mu;
    float v = d * d;
    #pragma unroll
    for (int o = 16; o > 0; o >>= 1) v += __shfl_xor_sync(0xffffffffu, v, o);
    if (l == 0) red2[w] = v;
    __syncthreads();
    float var = (red2[0] + red2[1] + red2[2] + red2[3]) * (1.0f / D);

    out[node * D + t] = d * rsqrtf(var + LN_EPS) * g[t] + b[t];
}

// In-degree count (int).
__global__ void count_kernel(const int* __restrict__ ei, int* __restrict__ deg) {
    int e = blockIdx.x * blockDim.x + threadIdx.x;
    if (e < N_EDGES) atomicAdd(&deg[ei[N_EDGES + e]], 1);
}

// Phase 1: per-block sum of 256 degrees.
__global__ __launch_bounds__(SCAN_B)
void block_sum_kernel(const int* __restrict__ deg, int* __restrict__ bsum) {
    __shared__ int ws[8];
    int node = blockIdx.x * SCAN_B + threadIdx.x;
    int d = (node < N_NODES) ? deg[node] : 0;
    int s = d;
    #pragma unroll
    for (int o = 16; o > 0; o >>= 1) s += __shfl_xor_sync(0xffffffffu, s, o);
    int w = threadIdx.x >> 5, l = threadIdx.x & 31;
    if (l == 0) ws[w] = s;
    __syncthreads();
    if (threadIdx.x == 0) {
        int tot = 0;
        #pragma unroll
        for (int i = 0; i < 8; i++) tot += ws[i];
        bsum[blockIdx.x] = tot;
    }
}

// Phase 2: exclusive scan of N_SB block sums. One block of 256 threads.
__global__ __launch_bounds__(256)
void scan_bsums_kernel(const int* __restrict__ bsum, int* __restrict__ boff) {
    __shared__ int sm[256];
    int t = threadIdx.x;
    int v = (t < N_SB) ? bsum[t] : 0;
    sm[t] = v;
    __syncthreads();
    for (int o = 1; o < 256; o <<= 1) {
        int u = (t >= o) ? sm[t - o] : 0;
        __syncthreads();
        sm[t] += u;
        __syncthreads();
    }
    if (t < N_SB) boff[t] = sm[t] - v;  // exclusive
}

// Phase 3: per-block exclusive scan + base offset -> row, cursor, invd.
__global__ __launch_bounds__(SCAN_B)
void expand_kernel(const int* __restrict__ deg,
                   const int* __restrict__ boff,
                   int* __restrict__ row,
                   int* __restrict__ cursor,
                   float* __restrict__ invd) {
    __shared__ int ws[8];
    __shared__ int wo[8];
    int t = threadIdx.x;
    int node = blockIdx.x * SCAN_B + t;
    int d = (node < N_NODES) ? deg[node] : 0;

    int incl = d;
    int l = t & 31, w = t >> 5;
    #pragma unroll
    for (int o = 1; o < 32; o <<= 1) {
        int u = __shfl_up_sync(0xffffffffu, incl, o);
        if (l >= o) incl += u;
    }
    if (l == 31) ws[w] = incl;
    __syncthreads();
    if (t == 0) {
        int run = 0;
        #pragma unroll
        for (int i = 0; i < 8; i++) { wo[i] = run; run += ws[i]; }
    }
    __syncthreads();

    if (node < N_NODES) {
        int excl = boff[blockIdx.x] + wo[w] + incl - d;
        row[node] = excl;
        cursor[node] = excl;
        invd[node] = 1.0f / fmaxf((float)d, 1.0f);
    }
    if (node == 0) row[N_NODES] = N_EDGES;
}

// Fill permutation: for each edge, place src into dst's CSR segment.
__global__ void build_perm_kernel(const int* __restrict__ ei,
                                  int* __restrict__ cursor,
                                  int* __restrict__ perm) {
    int e = blockIdx.x * blockDim.x + threadIdx.x;
    if (e >= N_EDGES) return;
    int dst = ei[N_EDGES + e];
    int pos = atomicAdd(&cursor[dst], 1);
    perm[pos] = ei[e];
}

// Mean-aggregate via CSR gather. One warp per node; lane = float4 chunk.
__global__ __launch_bounds__(256)
void gather_agg_kernel(const float* __restrict__ h,
                       const int* __restrict__ row,
                       const int* __restrict__ perm,
                       const float* __restrict__ invd,
                       float* __restrict__ agg) {
    int node = blockIdx.x * 8 + (threadIdx.x >> 5);
    int lane = threadIdx.x & 31;
    if (node >= N_NODES) return;
    int beg = row[node];
    int end = row[node + 1];

    float4 acc = make_float4(0.f, 0.f, 0.f, 0.f);
    for (int j = beg; j < end; j += 32) {
        int nj = min(32, end - j);
        int s = (j + lane < end) ? __ldg(&perm[j + lane]) : 0;
        int k = 0;
        for (; k + 4 <= nj; k += 4) {
            int s0 = __shfl_sync(0xffffffffu, s, k);
            int s1 = __shfl_sync(0xffffffffu, s, k + 1);
            int s2 = __shfl_sync(0xffffffffu, s, k + 2);
            int s3 = __shfl_sync(0xffffffffu, s, k + 3);
            float4 v0 = ((const float4*)h)[s0 * D4 + lane];
            float4 v1 = ((const float4*)h)[s1 * D4 + lane];
            float4 v2 = ((const float4*)h)[s2 * D4 + lane];
            float4 v3 = ((const float4*)h)[s3 * D4 + lane];
            acc.x += v0.x + v1.x + v2.x + v3.x;
            acc.y += v0.y + v1.y + v2.y + v3.y;
            acc.z += v0.z + v1.z + v2.z + v3.z;
            acc.w += v0.w + v1.w + v2.w + v3.w;
        }
        for (; k < nj; k++) {
            int sk = __shfl_sync(0xffffffffu, s, k);
            float4 v = ((const float4*)h)[sk * D4 + lane];
            acc.x += v.x; acc.y += v.y; acc.z += v.z; acc.w += v.w;
        }
    }
    float iv = invd[node];
    acc.x *= iv; acc.y *= iv; acc.z *= iv; acc.w *= iv;
    ((float4*)agg)[node * D4 + lane] = acc;
}

// out[n][c] = act( agg[n] . Wl[c] + bl[c] + h[n] . Wr[c] )   (agg pre-scaled)
// Weights given TRANSPOSED: WT[k][c]. Warp lanes load contiguous 512B spans.
// Block: 64 nodes x 128 cols, 256 threads, thread tile 8 nodes x 4 cols.
__global__ __launch_bounds__(256)
void combine_kernel(const float* __restrict__ agg,
                    const float* __restrict__ h,
                    const float* __restrict__ WTl,
                    const float* __restrict__ bl,
                    const float* __restrict__ WTr,
                    float* __restrict__ out,
                    int relu) {
    extern __shared__ float smem[];
    float* sa = smem;               // [TILE_N][D]
    float* sh = smem + TILE_N * D;  // [TILE_N][D]

    int n0 = blockIdx.x * TILE_N;
    int t = threadIdx.x;

    for (int i = t; i < TILE_N * D4; i += 256) {
        int r = i / D4;
        int c4 = i % D4;
        int node = n0 + r;
        float4 av = make_float4(0.f, 0.f, 0.f, 0.f);
        float4 hv = av;
        if (node < N_NODES) {
            av = ((const float4*)agg)[node * D4 + c4];
            hv = ((const float4*)h)[node * D4 + c4];
        }
        ((float4*)&sa[r * D])[c4] = av;
        ((float4*)&sh[r * D])[c4] = hv;
    }
    __syncthreads();

    int cx = (t & 31) * 4;   // column base (0..124)
    int ny = (t >> 5) * 8;   // node base within tile (0..56)

    float acc[8][4];
    #pragma unroll
    for (int n = 0; n < 8; n++)
        #pragma unroll
        for (int j = 0; j < 4; j++) acc[n][j] = 0.f;

    for (int k = 0; k < D; k += 4) {
        // wl[kk] = WTl[k+kk][cx..cx+3]  (coalesced: lanes cover contiguous 512B)
        float4 wl[4], wr[4];
        #pragma unroll
        for (int kk = 0; kk < 4; kk++) {
            wl[kk] = __ldg((const float4*)&WTl[(k + kk) * D + cx]);
            wr[kk] = __ldg((const float4*)&WTr[(k + kk) * D + cx]);
        }
        #pragma unroll
        for (int n = 0; n < 8; n++) {
            float4 a4 = *(const float4*)&sa[(ny + n) * D + k];  // broadcast LDS
            float4 h4 = *(const float4*)&sh[(ny + n) * D + k];
            #pragma unroll
            for (int j = 0; j < 4; j++) {
                float r = acc[n][j];
                r = fmaf(a4.x, ((const float*)&wl[0])[j], r);
                r = fmaf(a4.y, ((const float*)&wl[1])[j], r);
                r = fmaf(a4.z, ((const float*)&wl[2])[j], r);
                r = fmaf(a4.w, ((const float*)&wl[3])[j], r);
                r = fmaf(h4.x, ((const float*)&wr[0])[j], r);
                r = fmaf(h4.y, ((const float*)&wr[1])[j], r);
                r = fmaf(h4.z, ((const float*)&wr[2])[j], r);
                r = fmaf(h4.w, ((const float*)&wr[3])[j], r);
                acc[n][j] = r;
            }
        }
    }

    float4 bias = __ldg((const float4*)&bl[cx]);
    #pragma unroll
    for (int n = 0; n < 8; n++) {
        int node = n0 + ny + n;
        if (node < N_NODES) {
            float4 o;
            o.x = acc[n][0] + bias.x;
            o.y = acc[n][1] + bias.y;
            o.z = acc[n][2] + bias.z;
            o.w = acc[n][3] + bias.w;
            if (relu) {
                o.x = fmaxf(o.x, 0.f);
                o.y = fmaxf(o.y, 0.f);
                o.z = fmaxf(o.z, 0.f);
                o.w = fmaxf(o.w, 0.f);
            }
            ((float4*)out)[node * D4 + (cx >> 2)] = o;
        }
    }
}

// ---------------- launch ----------------

extern "C" void kernel_launch(void* const* d_in, const int* in_sizes, int n_in,
                              void* d_out, int out_size) {
    const int*   x    = (const int*)d_in[0];
    const int*   ei   = (const int*)d_in[1];
    const float* syn  = (const float*)d_in[2];
    const float* lem  = (const float*)d_in[3];
    const float* pos  = (const float*)d_in[4];
    const float* sen  = (const float*)d_in[5];
    const float* ln_g = (const float*)d_in[6];
    const float* ln_b = (const float*)d_in[7];
    const float* Wl0  = (const float*)d_in[8];
    const float* bl0  = (const float*)d_in[9];
    const float* Wr0  = (const float*)d_in[10];
    const float* Wl1  = (const float*)d_in[11];
    const float* bl1  = (const float*)d_in[12];
    const float* Wr1  = (const float*)d_in[13];
    float* out = (float*)d_out;

    float *h0, *h1, *agg, *invd, *wt;
    int *deg, *row, *cursor, *perm, *bsum, *boff;
    cudaGetSymbolAddress((void**)&h0,     g_h0);
    cudaGetSymbolAddress((void**)&h1,     g_h1);
    cudaGetSymbolAddress((void**)&agg,    g_agg);
    cudaGetSymbolAddress((void**)&deg,    g_deg);
    cudaGetSymbolAddress((void**)&row,    g_row);
    cudaGetSymbolAddress((void**)&cursor, g_cursor);
    cudaGetSymbolAddress((void**)&invd,   g_invd);
    cudaGetSymbolAddress((void**)&perm,   g_perm);
    cudaGetSymbolAddress((void**)&bsum,   g_bsum);
    cudaGetSymbolAddress((void**)&boff,   g_boff);
    cudaGetSymbolAddress((void**)&wt,     g_WT);

    static const int smem_bytes = TILE_N * D * 4 * 2;  // 64 KB
    cudaFuncSetAttribute(combine_kernel,
                         cudaFuncAttributeMaxDynamicSharedMemorySize, smem_bytes);

    const int eblocks = (N_EDGES + 255) / 256;
    const int gather_blocks = (N_NODES + 7) / 8;
    const int combine_blocks = (N_NODES + TILE_N - 1) / TILE_N;

    // 0. transpose weights (WT[k][c])
    transpose_w_kernel<<<(4 * D * D + 255) / 256, 256>>>(Wl0, Wr0, Wl1, Wr1, wt);

    // 1. embeddings + LayerNorm -> h0
    embed_ln_kernel<<<N_NODES, 128>>>(x, syn, lem, pos, sen, ln_g, ln_b, h0);

    // 2. CSR build (parallel scan)
    zero_int_kernel<<<(N_NODES + 255) / 256, 256>>>(deg, N_NODES);
    count_kernel<<<eblocks, 256>>>(ei, deg);
    block_sum_kernel<<<N_SB, SCAN_B>>>(deg, bsum);
    scan_bsums_kernel<<<1, 256>>>(bsum, boff);
    expand_kernel<<<N_SB, SCAN_B>>>(deg, boff, row, cursor, invd);
    build_perm_kernel<<<eblocks, 256>>>(ei, cursor, perm);

    // 3. layer 0
    gather_agg_kernel<<<gather_blocks, 256>>>(h0, row, perm, invd, agg);
    combine_kernel<<<combine_blocks, 256, smem_bytes>>>(agg, h0,
        wt + 0 * D * D, bl0, wt + 1 * D * D, h1, 1);

    // 4. layer 1
    gather_agg_kernel<<<gather_blocks, 256>>>(h1, row, perm, invd, agg);
    combine_kernel<<<combine_blocks, 256, smem_bytes>>>(agg, h1,
        wt + 2 * D * D, bl1, wt + 3 * D * D, out, 0);
}